// round 13
// baseline (speedup 1.0000x reference)
#include <cuda_runtime.h>
#include <cuda_fp16.h>
#include <cstdint>

// ---------------- problem constants ----------------
#define BATCH   65536
#define IN_F    1024
#define OUT_F   1024
#define BM      128
#define BN      128
#define BK      32
#define NK      (IN_F / BK)      // 32 k-chunks
#define NTHREADS 256
#define STAGES  4

// stage: A fp32 128x32 = 16KB (128B rows), B fp16 128x32 = 8KB (64B rows)
#define STAGE_BYTES 24576
#define B_OFF       16384
#define SMEM_PAD    2048
#define SMEM_TOTAL  (SMEM_PAD + STAGES * STAGE_BYTES)   // 100352 -> 2 CTAs/SM

// fp16 W copy, k permuted by sigma=(0,4,1,5,2,6,3,7) within each 8-group —
// matches the (t, t+4) pairing from fp32-ldmatrix + f16x2 pack on A.
__device__ __half g_Wh[(size_t)OUT_F * IN_F];

// ---------------- helpers ----------------
__device__ __forceinline__ uint32_t h2_u32(__half2 h) {
    union { __half2 h; uint32_t u; } c; c.h = h; return c.u;
}
__device__ __forceinline__ uint32_t pack_rn(uint32_t lo_bits, uint32_t hi_bits) {
    return h2_u32(__floats2half2_rn(__uint_as_float(lo_bits), __uint_as_float(hi_bits)));
}
__device__ __forceinline__ uint32_t smem_u32(const void* p) {
    uint32_t a;
    asm("{ .reg .u64 t; cvta.to.shared.u64 t, %1; cvt.u32.u64 %0, t; }" : "=r"(a) : "l"(p));
    return a;
}
__device__ __forceinline__ void cp16(uint32_t s, const void* g) {
    asm volatile("cp.async.cg.shared.global [%0], [%1], 16;" :: "r"(s), "l"(g));
}
#define CP_COMMIT() asm volatile("cp.async.commit_group;" ::: "memory")
#define CP_WAIT(n)  asm volatile("cp.async.wait_group %0;" :: "n"(n) : "memory")

#define LDSM4(R, A) \
    asm volatile("ldmatrix.sync.aligned.m8n8.x4.shared.b16 {%0,%1,%2,%3}, [%4];" \
        : "=r"((R)[0]), "=r"((R)[1]), "=r"((R)[2]), "=r"((R)[3]) : "r"(A))

#define MMA_F16(D, A, B0, B1) \
    asm volatile("mma.sync.aligned.m16n8k16.row.col.f32.f16.f16.f32 " \
        "{%0,%1,%2,%3}, {%4,%5,%6,%7}, {%8,%9}, {%0,%1,%2,%3};" \
        : "+f"((D)[0]), "+f"((D)[1]), "+f"((D)[2]), "+f"((D)[3]) \
        : "r"((A)[0]), "r"((A)[1]), "r"((A)[2]), "r"((A)[3]), "r"(B0), "r"(B1))

__device__ __forceinline__ float tanh_ap(float x) {
    float y; asm("tanh.approx.f32 %0, %1;" : "=f"(y) : "f"(x)); return y;
}
__device__ __forceinline__ float sin_ap(float x) {
    float y; asm("sin.approx.f32 %0, %1;" : "=f"(y) : "f"(x)); return y;
}

// ---------------- W conversion with per-8-group k permutation ----------------
__global__ void __launch_bounds__(256) cvt_w_perm_kernel(const float4* __restrict__ in) {
    size_t i = (size_t)blockIdx.x * 256 + threadIdx.x;   // one 8-float k-group
    float4 v0 = in[2 * i];       // k 0-3
    float4 v1 = in[2 * i + 1];   // k 4-7
    uint4 o = { h2_u32(__floats2half2_rn(v0.x, v1.x)),   // (0,4)
                h2_u32(__floats2half2_rn(v0.y, v1.y)),   // (1,5)
                h2_u32(__floats2half2_rn(v0.z, v1.z)),   // (2,6)
                h2_u32(__floats2half2_rn(v0.w, v1.w)) }; // (3,7)
    ((uint4*)g_Wh)[i] = o;
}

// ---------------- fused GEMM: A fp32 (in-flight convert) x B fp16 ----------------
__global__ void __launch_bounds__(NTHREADS, 2)
gemm_act_kernel(const float* __restrict__ X, const float* __restrict__ Bv,
                float* __restrict__ O) {
    extern __shared__ char smem[];
    const uint32_t sb = smem_u32(smem);
    const uint32_t tiles = ((sb + 127) & ~127u) + SMEM_PAD - 128;

    const int tid = threadIdx.x;
    const int wid = tid >> 5;
    const int lane = tid & 31;
    const int warp_m = wid & 3;       // 0..3 -> m offset *32
    const int warp_n = wid >> 2;      // 0..1 -> n offset *64

    const int nt = blockIdx.x & 7;    // 8 N-tiles share one A tile via L2
    const int mt = blockIdx.x >> 3;   // 512 M-tiles
    const int m0 = mt * BM;
    const int n0 = nt * BN;

    // ---- producer addressing ----
    // A fp32: 128 rows x 128B; thread -> rows rr+32i (i<4), vec cc
    const int rr = tid >> 3;                  // 0..31
    const int cc = tid & 7;                   // 16B vec in 128B row
    const uint32_t offA0 = (uint32_t)(rr * 128 + ((cc * 16) ^ ((rr & 7) << 4)));
    const float* gAt = X + (size_t)(m0 + rr) * IN_F + cc * 4;
    // B fp16: 128 rows x 64B; thread -> rows rb+64i (i<2), vec cb2 (R7-verified)
    const int rb = tid >> 2;                  // 0..63
    const int cb2 = tid & 3;
    const uint32_t offB0 = (uint32_t)(B_OFF + rb * 64 + ((cb2 * 16) ^ ((rb & 8) << 2)));
    const __half* gBt = g_Wh + (size_t)(n0 + rb) * IN_F + cb2 * 8;

    // ---- consumer per-lane constants ----
    // A fp32 ldmatrix (128B rows): x4 tiles = rows0-7 | rows0-7+16B | rows8-15 | +16B
    const int rowA = warp_m * 32 + (lane & 7) + ((lane >> 4) << 3);
    const uint32_t aBase = (uint32_t)(rowA * 128);
    const uint32_t aSw   = (uint32_t)((rowA & 7) << 4);
    const uint32_t aSel  = (uint32_t)(((lane >> 3) & 1) * 16);
    // B fp16 ldmatrix (64B rows, R7-verified)
    const int brow = warp_n * 64 + (lane & 7) + ((lane >> 4) << 3);
    const uint32_t bRowOff = (uint32_t)(B_OFF + brow * 64);
    const uint32_t swB     = (uint32_t)((brow & 8) << 2);
    const uint32_t k16     = (uint32_t)(((lane >> 3) & 1) * 16);

    float acc[2][8][4];
    #pragma unroll
    for (int a = 0; a < 2; ++a)
        #pragma unroll
        for (int f = 0; f < 8; ++f)
            #pragma unroll
            for (int c = 0; c < 4; ++c) acc[a][f][c] = 0.0f;

    // ---- prologue: stages 0..2 ----
    #pragma unroll
    for (int s = 0; s < 3; ++s) {
        const uint32_t base = tiles + s * STAGE_BYTES;
        const float*  a = gAt + s * BK;
        const __half* b = gBt + s * BK;
        #pragma unroll
        for (int i = 0; i < 4; ++i)
            cp16(base + offA0 + i * 4096, a + (size_t)i * 32 * IN_F);
        #pragma unroll
        for (int i = 0; i < 2; ++i)
            cp16(base + offB0 + i * 4096, b + (size_t)i * 64 * IN_F);
        CP_COMMIT();
    }

    // ---- mainloop (rotating stage offsets) ----
    uint32_t stg_cons = tiles;                               // stage kc
    uint32_t stg_prod = tiles + 3 * STAGE_BYTES;             // stage kc+3
    const uint32_t stg_top = tiles + (STAGES - 1) * STAGE_BYTES;
    for (int kc = 0; kc < NK; ++kc) {
        CP_WAIT(2);
        __syncthreads();

        if (kc + 3 < NK) {
            const float*  a = gAt + (kc + 3) * BK;
            const __half* b = gBt + (kc + 3) * BK;
            #pragma unroll
            for (int i = 0; i < 4; ++i)
                cp16(stg_prod + offA0 + i * 4096, a + (size_t)i * 32 * IN_F);
            #pragma unroll
            for (int i = 0; i < 2; ++i)
                cp16(stg_prod + offB0 + i * 4096, b + (size_t)i * 64 * IN_F);
        }
        CP_COMMIT();   // one group per kc keeps the wait-count invariant

        const uint32_t aA = stg_cons + aBase;
        const uint32_t bR = stg_cons + bRowOff;
        #pragma unroll
        for (int j = 0; j < 2; ++j) {         // 2 x k16 steps per BK=32
            // ---- A fragments: fp32 ldmatrix + RN pack (k-pairing (t, t+4)) ----
            uint32_t f0[4], f1[4], g0[4], g1[4];
            LDSM4(f0, aA + ((j * 64 + aSel) ^ aSw));              // m 0-15, k lo 8-grp
            LDSM4(f1, aA + ((j * 64 + 32 + aSel) ^ aSw));         // m 0-15, k hi 8-grp
            LDSM4(g0, aA + 2048 + ((j * 64 + aSel) ^ aSw));       // m 16-31, lo
            LDSM4(g1, aA + 2048 + ((j * 64 + 32 + aSel) ^ aSw));  // m 16-31, hi
            uint32_t a0[4], a1[4];
            a0[0] = pack_rn(f0[0], f0[1]);
            a0[1] = pack_rn(f0[2], f0[3]);
            a0[2] = pack_rn(f1[0], f1[1]);
            a0[3] = pack_rn(f1[2], f1[3]);
            a1[0] = pack_rn(g0[0], g0[1]);
            a1[1] = pack_rn(g0[2], g0[3]);
            a1[2] = pack_rn(g1[0], g1[1]);
            a1[3] = pack_rn(g1[2], g1[3]);
            // ---- B quarters + MMAs (R7-verified addressing) ----
            const uint32_t kB = (uint32_t)(j * 32 + k16) ^ swB;
            #pragma unroll
            for (int q = 0; q < 4; ++q) {
                uint32_t b[4];
                LDSM4(b, bR + q * 1024 + kB);
                MMA_F16(acc[0][2 * q],     a0, b[0], b[1]);
                MMA_F16(acc[1][2 * q],     a1, b[0], b[1]);
                MMA_F16(acc[0][2 * q + 1], a0, b[2], b[3]);
                MMA_F16(acc[1][2 * q + 1], a1, b[2], b[3]);
            }
        }
        stg_cons = (stg_cons == stg_top) ? tiles : stg_cons + STAGE_BYTES;
        stg_prod = (stg_prod == stg_top) ? tiles : stg_prod + STAGE_BYTES;
    }

    // ---- epilogue: bias + cyclic activations, staged through smem ----
    CP_WAIT(0);
    __syncthreads();    // tiles no longer needed; reuse smem as output staging

    float bs0[8], bs1[8];
    #pragma unroll
    for (int f = 0; f < 8; ++f) {
        const int cbn = n0 + warp_n * 64 + f * 8 + 2 * (lane & 3);
        bs0[f] = __ldg(Bv + cbn);
        bs1[f] = __ldg(Bv + cbn + 1);
    }

    float* eb = (float*)(smem + (tiles - sb));    // stride-136 staging, 128 rows
    const bool even = (lane & 1) == 0;

    #pragma unroll
    for (int mf = 0; mf < 2; ++mf) {
        #pragma unroll
        for (int h = 0; h < 2; ++h) {
            const int row = warp_m * 32 + mf * 16 + (lane >> 2) + h * 8;
            #pragma unroll
            for (int f = 0; f < 8; ++f) {
                float v0 = acc[mf][f][2 * h]     + bs0[f];
                float v1 = acc[mf][f][2 * h + 1] + bs1[f];
                float o0 = even ? tanh_ap(v0) : fmaxf(v0, 0.0f);            // col%4 0|2
                float o1 = even ? sin_ap(v1)
                                : fmaf(0.5f, tanh_ap(0.5f * v1), 0.5f);     // col%4 1|3
                float2 o = { o0, o1 };
                *(float2*)&eb[(size_t)row * 136 + warp_n * 64 + f * 8 + 2 * (lane & 3)] = o;
            }
        }
    }
    __syncthreads();

    // coalesced 128B streaming stores: 128 rows x 32 float4
    #pragma unroll
    for (int i = 0; i < 16; ++i) {
        const int idx = tid + i * NTHREADS;
        const int row = idx >> 5;
        const int c4  = idx & 31;
        float4 v = *(const float4*)&eb[(size_t)row * 136 + c4 * 4];
        *(float4*)(O + (size_t)(m0 + row) * OUT_F + n0 + c4 * 4) = v;
    }
}

// ---------------- launch ----------------
extern "C" void kernel_launch(void* const* d_in, const int* in_sizes, int n_in,
                              void* d_out, int out_size) {
    const float* X  = (const float*)d_in[0];
    const float* Wt = (const float*)d_in[1];
    const float* Bv = (const float*)d_in[2];
    float* O = (float*)d_out;

    cvt_w_perm_kernel<<<(int)(((size_t)OUT_F * IN_F / 8) / 256), 256>>>((const float4*)Wt);

    cudaFuncSetAttribute(gemm_act_kernel,
                         cudaFuncAttributeMaxDynamicSharedMemorySize, SMEM_TOTAL);
    gemm_act_kernel<<<(BATCH / BM) * (OUT_F / BN), NTHREADS, SMEM_TOTAL>>>(X, Bv, O);
}

// round 14
// speedup vs baseline: 1.8943x; 1.8943x over previous
#include <cuda_runtime.h>
#include <cuda_fp16.h>
#include <cstdint>

// ---------------- problem constants ----------------
#define BATCH   65536
#define IN_F    1024
#define OUT_F   1024
#define BM      128
#define BN      128
#define BK      64
#define NK      (IN_F / BK)      // 16 k-chunks
#define NTHREADS 256
#define STAGES  3

#define STAGE_BYTES 32768        // A 16KB (128x64 f16) + B 16KB (128x64 f16)
#define B_OFF       16384
#define SMEM_PAD    2048
#define SMEM_TOTAL  (SMEM_PAD + STAGES * STAGE_BYTES)   // 100352 -> 2 CTAs/SM

// smem offsets (from dynamic smem base) for mbarriers
#define MB_FULL   0              // 3 x 8B
#define MB_EMPTY  24             // 3 x 8B

// fp16 copies (round-nearest). Same 10 mantissa bits as tf32; fp32 accumulate.
__device__ __half g_Xh[(size_t)BATCH * IN_F];   // 128 MB scratch
__device__ __half g_Wh[(size_t)OUT_F * IN_F];   // 2 MB scratch

// ---------------- helpers ----------------
__device__ __forceinline__ uint32_t h2_u32(__half2 h) {
    union { __half2 h; uint32_t u; } c; c.h = h; return c.u;
}
__device__ __forceinline__ uint32_t smem_u32(const void* p) {
    uint32_t a;
    asm("{ .reg .u64 t; cvta.to.shared.u64 t, %1; cvt.u32.u64 %0, t; }" : "=r"(a) : "l"(p));
    return a;
}
__device__ __forceinline__ void cp16(uint32_t s, const void* g) {
    asm volatile("cp.async.cg.shared.global [%0], [%1], 16;" :: "r"(s), "l"(g));
}

#define MBAR_INIT(addr, cnt) \
    asm volatile("mbarrier.init.shared.b64 [%0], %1;" :: "r"(addr), "r"(cnt) : "memory")
#define MBAR_ARRIVE(addr) \
    asm volatile("mbarrier.arrive.shared.b64 _, [%0];" :: "r"(addr) : "memory")
#define CP_ARRIVE_NOINC(addr) \
    asm volatile("cp.async.mbarrier.arrive.noinc.shared::cta.b64 [%0];" :: "r"(addr) : "memory")

#define MBAR_WAIT_PARITY(addr, par) do {                                          \
    uint32_t _m = (addr); uint32_t _p = (par); uint32_t _d;                       \
    asm volatile("{\n\t.reg .pred p;\n\t"                                         \
        "mbarrier.try_wait.parity.acquire.cta.shared::cta.b64 p, [%1], %2;\n\t"   \
        "selp.b32 %0, 1, 0, p;\n\t}"                                              \
        : "=r"(_d) : "r"(_m), "r"(_p) : "memory");                                \
    if (!_d) {                                                                    \
        asm volatile("{\n\t.reg .pred P1;\n\t"                                    \
            "WL_%=:\n\t"                                                          \
            "mbarrier.try_wait.parity.acquire.cta.shared::cta.b64 P1, [%0], %1, 0x989680;\n\t" \
            "@P1 bra.uni WD_%=;\n\t"                                              \
            "bra.uni WL_%=;\n\t"                                                  \
            "WD_%=:\n\t}" :: "r"(_m), "r"(_p) : "memory");                        \
    } } while (0)

#define LDSM4(R, A) \
    asm volatile("ldmatrix.sync.aligned.m8n8.x4.shared.b16 {%0,%1,%2,%3}, [%4];" \
        : "=r"((R)[0]), "=r"((R)[1]), "=r"((R)[2]), "=r"((R)[3]) : "r"(A))

#define MMA_F16(D, A, B0, B1) \
    asm volatile("mma.sync.aligned.m16n8k16.row.col.f32.f16.f16.f32 " \
        "{%0,%1,%2,%3}, {%4,%5,%6,%7}, {%8,%9}, {%0,%1,%2,%3};" \
        : "+f"((D)[0]), "+f"((D)[1]), "+f"((D)[2]), "+f"((D)[3]) \
        : "r"((A)[0]), "r"((A)[1]), "r"((A)[2]), "r"((A)[3]), "r"(B0), "r"(B1))

__device__ __forceinline__ float tanh_ap(float x) {
    float y; asm("tanh.approx.f32 %0, %1;" : "=f"(y) : "f"(x)); return y;
}
__device__ __forceinline__ float sin_ap(float x) {
    float y; asm("sin.approx.f32 %0, %1;" : "=f"(y) : "f"(x)); return y;
}

// ---------------- conversion: X then W in one launch (fp32 -> fp16 RN) ----------
#define XVECS ((size_t)BATCH * IN_F / 8)
__global__ void __launch_bounds__(256)
cvt_xw_kernel(const float4* __restrict__ Xin, const float4* __restrict__ Win) {
    size_t i = (size_t)blockIdx.x * 256 + threadIdx.x;
    const float4* src;
    uint4* dst;
    if (i < XVECS) { src = Xin + 2 * i; dst = (uint4*)g_Xh + i; }
    else           { size_t j = i - XVECS; src = Win + 2 * j; dst = (uint4*)g_Wh + j; }
    float4 v0 = src[0], v1 = src[1];
    uint4 o = { h2_u32(__floats2half2_rn(v0.x, v0.y)),
                h2_u32(__floats2half2_rn(v0.z, v0.w)),
                h2_u32(__floats2half2_rn(v1.x, v1.y)),
                h2_u32(__floats2half2_rn(v1.z, v1.w)) };
    *dst = o;
}

// ---------------- fused fp16 GEMM (fp32 accum) + cyclic activations ----------------
__global__ void __launch_bounds__(NTHREADS, 2)
gemm_act_kernel(const float* __restrict__ Bv, float* __restrict__ O) {
    extern __shared__ char smem[];
    const uint32_t sb = smem_u32(smem);
    const uint32_t tiles = ((sb + 127) & ~127u) + SMEM_PAD - 128;

    const int tid = threadIdx.x;
    const int wid = tid >> 5;
    const int lane = tid & 31;
    const int warp_m = wid & 3;       // 0..3 -> m offset *32
    const int warp_n = wid >> 2;      // 0..1 -> n offset *64

    const int nt = blockIdx.x & 7;    // 8 N-tiles; consecutive bids share A tile in L2
    const int mt = blockIdx.x >> 3;   // 512 M-tiles
    const int m0 = mt * BM;
    const int n0 = nt * BN;

    // ---- mbarrier init ----
    if (tid == 0) {
        #pragma unroll
        for (int s = 0; s < STAGES; ++s) {
            MBAR_INIT(sb + MB_FULL  + s * 8, NTHREADS);   // cp.async completions
            MBAR_INIT(sb + MB_EMPTY + s * 8, NTHREADS);   // consumer arrivals
        }
    }
    __syncthreads();

    // ---- producer addressing: row = 128B of fp16 (64 halves) ----
    const int rr = tid >> 3;                  // 0..31
    const int cc = tid & 7;                   // 16B vec
    const uint32_t sw_base = (uint32_t)((cc * 16) ^ ((rr & 7) << 4));
    const __half* gAt = g_Xh + (size_t)(m0 + rr) * IN_F + cc * 8;
    const __half* gBt = g_Wh + (size_t)(n0 + rr) * IN_F + cc * 8;

    // ---- ldmatrix per-thread offsets ----
    const int arow = warp_m * 32 + (lane & 15);
    const uint32_t offA = (uint32_t)(arow * 128 + (((lane >> 4) * 16) ^ ((arow & 7) << 4)));
    const int brow = warp_n * 64 + (lane & 7) + ((lane >> 4) << 3);
    const uint32_t offB = (uint32_t)(brow * 128 + ((((lane >> 3) & 1) * 16) ^ ((brow & 7) << 4)))
                        + B_OFF;

    float acc[2][8][4];
    #pragma unroll
    for (int a = 0; a < 2; ++a)
        #pragma unroll
        for (int f = 0; f < 8; ++f)
            #pragma unroll
            for (int c = 0; c < 4; ++c) acc[a][f][c] = 0.0f;

    // ---- prologue: produce stages 0..2 (productions p=0, no empty wait) ----
    #pragma unroll
    for (int s = 0; s < STAGES; ++s) {
        const uint32_t base = tiles + s * STAGE_BYTES + rr * 128 + sw_base;
        const __half* a = gAt + s * BK;
        const __half* b = gBt + s * BK;
        #pragma unroll
        for (int i = 0; i < 4; ++i) {         // A,B: 4 x 32 rows each
            cp16(base + i * 4096,         a + (size_t)i * 32 * IN_F);
            cp16(base + B_OFF + i * 4096, b + (size_t)i * 32 * IN_F);
        }
        CP_ARRIVE_NOINC(sb + MB_FULL + s * 8);
    }

    // ---- mainloop: mbarrier flow control, no CTA-wide barriers ----
    uint32_t stg_cons = tiles;
    const uint32_t stg_top = tiles + (STAGES - 1) * STAGE_BYTES;
    int sidx = 0;          // kc % 3
    int phase = 0;         // (kc / 3) & 1
    for (int kc = 0; kc < NK; ++kc) {
        // wait until stage resident (all 256 threads' cp.asyncs for it done)
        MBAR_WAIT_PARITY(sb + MB_FULL + sidx * 8, phase);

        const uint32_t aB = stg_cons + offA;
        const uint32_t bB = stg_cons + offB;
        #pragma unroll
        for (int j = 0; j < 4; ++j) {         // 4 x k16 steps per BK=64
            const uint32_t jx = (uint32_t)(j << 5);
            const uint32_t ax = aB ^ jx;
            const uint32_t bx = bB ^ jx;
            uint32_t a0[4], a1[4];
            LDSM4(a0, ax);                          // m 0-15
            LDSM4(a1, ax + 2048);                   // m 16-31
            #pragma unroll
            for (int q = 0; q < 4; ++q) {           // n 16-blocks, 4 live B regs
                uint32_t b[4];
                LDSM4(b, bx + q * 2048);
                MMA_F16(acc[0][2 * q],     a0, b[0], b[1]);
                MMA_F16(acc[1][2 * q],     a1, b[0], b[1]);
                MMA_F16(acc[0][2 * q + 1], a0, b[2], b[3]);
                MMA_F16(acc[1][2 * q + 1], a1, b[2], b[3]);
            }
        }
        // this thread is done reading stage sidx
        MBAR_ARRIVE(sb + MB_EMPTY + sidx * 8);

        // refill the same stage with chunk kc+3 (production p = kc/3 + 1)
        if (kc + 3 < NK) {
            MBAR_WAIT_PARITY(sb + MB_EMPTY + sidx * 8, phase);  // all consumed
            const uint32_t base = stg_cons + rr * 128 + sw_base;
            const __half* a = gAt + (kc + 3) * BK;
            const __half* b = gBt + (kc + 3) * BK;
            #pragma unroll
            for (int i = 0; i < 4; ++i) {
                cp16(base + i * 4096,         a + (size_t)i * 32 * IN_F);
                cp16(base + B_OFF + i * 4096, b + (size_t)i * 32 * IN_F);
            }
            CP_ARRIVE_NOINC(sb + MB_FULL + sidx * 8);
        }

        if (stg_cons == stg_top) { stg_cons = tiles; sidx = 0; phase ^= 1; }
        else                     { stg_cons += STAGE_BYTES; ++sidx; }
    }

    // ---- epilogue: bias + cyclic activations, staged through smem ----
    __syncthreads();    // all compute done; reuse smem as output staging

    float bs0[8], bs1[8];
    #pragma unroll
    for (int f = 0; f < 8; ++f) {
        const int cb = n0 + warp_n * 64 + f * 8 + 2 * (lane & 3);
        bs0[f] = __ldg(Bv + cb);
        bs1[f] = __ldg(Bv + cb + 1);
    }

    float* eb = (float*)(smem + (tiles - sb));    // stride-136 staging, 128 rows
    const bool even = (lane & 1) == 0;

    #pragma unroll
    for (int mf = 0; mf < 2; ++mf) {
        #pragma unroll
        for (int h = 0; h < 2; ++h) {
            const int row = warp_m * 32 + mf * 16 + (lane >> 2) + h * 8;
            #pragma unroll
            for (int f = 0; f < 8; ++f) {
                float v0 = acc[mf][f][2 * h]     + bs0[f];
                float v1 = acc[mf][f][2 * h + 1] + bs1[f];
                float o0 = even ? tanh_ap(v0) : fmaxf(v0, 0.0f);            // col%4 0|2
                float o1 = even ? sin_ap(v1)
                                : fmaf(0.5f, tanh_ap(0.5f * v1), 0.5f);     // col%4 1|3
                float2 o = { o0, o1 };
                *(float2*)&eb[(size_t)row * 136 + warp_n * 64 + f * 8 + 2 * (lane & 3)] = o;
            }
        }
    }
    __syncthreads();

    // coalesced 128B streaming stores: 128 rows x 32 float4
    #pragma unroll
    for (int i = 0; i < 16; ++i) {
        const int idx = tid + i * NTHREADS;
        const int row = idx >> 5;
        const int c4  = idx & 31;
        float4 v = *(const float4*)&eb[(size_t)row * 136 + c4 * 4];
        *(float4*)(O + (size_t)(m0 + row) * OUT_F + n0 + c4 * 4) = v;
    }
}

// ---------------- launch ----------------
extern "C" void kernel_launch(void* const* d_in, const int* in_sizes, int n_in,
                              void* d_out, int out_size) {
    const float* X  = (const float*)d_in[0];
    const float* Wt = (const float*)d_in[1];
    const float* Bv = (const float*)d_in[2];
    float* O = (float*)d_out;

    const size_t total_vecs = XVECS + (size_t)OUT_F * IN_F / 8;
    cvt_xw_kernel<<<(int)(total_vecs / 256), 256>>>((const float4*)X, (const float4*)Wt);

    cudaFuncSetAttribute(gemm_act_kernel,
                         cudaFuncAttributeMaxDynamicSharedMemorySize, SMEM_TOTAL);
    gemm_act_kernel<<<(BATCH / BM) * (OUT_F / BN), NTHREADS, SMEM_TOTAL>>>(Bv, O);
}